// round 17
// baseline (speedup 1.0000x reference)
#include <cuda_runtime.h>
#include <math.h>
#include <stdint.h>

#define BXC 2
#define SXC 2048
#define FXC 512
#define IXC 1024
#define KXC 3
#define LXC 2
#define CXC 256

#define PI_F 3.14159265358979323846f

// ---------------- scratch (device globals; no allocation allowed) ------------
__device__ float g_a  [BXC*FXC*SXC];
__device__ float g_b  [BXC*FXC*SXC];
__device__ float g_h  [BXC*FXC*SXC];
__device__ float g_y1 [3*BXC*IXC*SXC];          // [branch][b][i][s]
__device__ float g_y2 [3*BXC*IXC*SXC];          // [branch][b][i][s]
__device__ float g_ds3[3*BXC*FXC*SXC];          // [branch(d,sc,sh)][b][f][s]
__device__ float g_str[BXC*2*FXC*SXC];
__device__ float g_log[BXC*CXC*SXC];
__device__ float g_fe [FXC];
__device__ float g_nll[BXC*SXC];

// packed bf16x2 weights (k-pairs in one u32; lo = even k, hi = odd k)
__device__ uint32_t g_wp0[6 * IXC * (FXC/2)];      // conv0: [sl][m][kp]    (256/row)
__device__ uint32_t g_wp3[6 * IXC * 3 * (IXC/2)];  // conv1: [sl][m][t][kp] (1536/row)
__device__ uint32_t g_wp2[6 * FXC * (IXC/2)];      // conv2: [sl][m][kp]    (512/row)
__device__ uint32_t g_wpL[CXC * FXC];              // logits: [m][kp]       (512/row)

__device__ __forceinline__ uint32_t pk(float lo, float hi) {
    uint32_t r;
    asm("cvt.rn.bf16x2.f32 %0, %1, %2;" : "=r"(r) : "f"(hi), "f"(lo));
    return r;
}

// ---------------- fused pre-pack (+ feature embedding) -----------------------
__global__ void pack_all(const float* __restrict__ w1s,
                         const float* __restrict__ w0s,
                         const float* __restrict__ w2s,
                         const float* __restrict__ out_w) {
    const int T3 = 6 * IXC * 3 * (IXC/2);
    const int T0 = 6 * IXC * (FXC/2);
    const int T2 = 6 * FXC * (IXC/2);
    const int TL = CXC * FXC;
    int i = blockIdx.x * 256 + threadIdx.x;
    if (i < T3) {
        int kp = i & 511;
        int t  = (i >> 9) % 3;
        int m6 = i / 1536;
        const float* src = w1s + (size_t)m6 * (IXC * 3) + (size_t)kp * 6 + t;
        g_wp3[i] = pk(src[0], src[3]);
        return;
    }
    i -= T3;
    if (i < T0) {
        float2 v = *(const float2*)&w0s[(size_t)2 * i];
        g_wp0[i] = pk(v.x, v.y);
        return;
    }
    i -= T0;
    if (i < T2) {
        float2 v = *(const float2*)&w2s[(size_t)2 * i];
        g_wp2[i] = pk(v.x, v.y);
        return;
    }
    i -= T2;
    if (i < TL) {
        float2 v = *(const float2*)&out_w[(size_t)2 * i];
        g_wpL[i] = pk(v.x, v.y);
        return;
    }
    i -= TL;
    if (i < FXC) {
        float ff = (float)i + 1.0f;
        float additive = fmodf(ff, 2.0f);
        float g = (ff - additive) * 0.5f;
        g = g * (8.0f / (float)FXC) - logf((float)CXC / (2.0f * PI_F));
        g_fe[i] = expf(g) + additive * PI_F;
    }
}

// ---------------- embedding gather (also builds h = b + fe) -------------------
__global__ void embed_kernel(const int* __restrict__ inp,
                             const float* __restrict__ emb) {
    size_t idx = (size_t)blockIdx.x * blockDim.x + threadIdx.x;
    if (idx >= (size_t)BXC * FXC * SXC) return;
    int s = (int)(idx % SXC);
    int f = (int)((idx / SXC) % FXC);
    int b = (int)(idx / ((size_t)SXC * FXC));
    int tok = inp[b * SXC + s];
    float av = emb[(size_t)tok * (2 * FXC) + f];
    float bv = emb[(size_t)tok * (2 * FXC) + FXC + f];
    g_a[idx] = av;
    g_b[idx] = bv;
    g_h[idx] = bv + g_fe[f];
    (void)s;
}

// ================= bf16 tensor-core conv-GEMM ================================
#define CP16(d, s)  asm volatile("cp.async.cg.shared.global [%0], [%1], 16;" :: "r"(d), "l"(s))
#define CPCOMMIT()  asm volatile("cp.async.commit_group;")
#define CPWAIT0()   asm volatile("cp.async.wait_group 0;")

__device__ __forceinline__ void mma_bf16(float* c, const uint32_t* a, const uint32_t* b) {
    asm volatile(
        "mma.sync.aligned.m16n8k16.row.col.f32.bf16.bf16.f32 "
        "{%0,%1,%2,%3}, {%4,%5,%6,%7}, {%8,%9}, {%0,%1,%2,%3};"
        : "+f"(c[0]), "+f"(c[1]), "+f"(c[2]), "+f"(c[3])
        : "r"(a[0]), "r"(a[1]), "r"(a[2]), "r"(a[3]), "r"(b[0]), "r"(b[1]));
}

__device__ __forceinline__ void ldsm4(uint32_t& r0, uint32_t& r1, uint32_t& r2, uint32_t& r3,
                                      uint32_t addr) {
    asm volatile("ldmatrix.sync.aligned.m8n8.x4.shared.b16 {%0,%1,%2,%3}, [%4];"
                 : "=r"(r0), "=r"(r1), "=r"(r2), "=r"(r3) : "r"(addr));
}

// z = blockIdx.z indexes (branch*BXC + b) for batched convs, or just b.
// X is [z][Kd][N]. A row stride ApS (u32); per-branch A offset AzStride (u32).
// YSPLIT: Y is [branch][BXC][1024][N] with m spanning 3*1024.
template <int TAPS, bool RELU, bool BIAS, bool YSPLIT>
__global__ __launch_bounds__(256, 2)
void mmbf(const uint32_t* __restrict__ Ap,
          const float* __restrict__ X,
          float* __restrict__ Y,
          const float* __restrict__ bias,
          int M, int Kd, int N, int ApS, size_t AzStride) {
    constexpr int AC   = 16 * TAPS;
    constexpr int AST  = AC + 4;          // 52 / 20 u32 rows (208/80 B: 16B-aligned)
    constexpr int XOFF = 4;
    constexpr int XST  = 136;
    constexpr int ASZ  = 128 * AST;
    constexpr int XSZ  = 16 * XST;

    extern __shared__ uint32_t sm[];
    uint32_t* As0 = sm;
    uint32_t* As1 = sm + ASZ;
    uint32_t* Xs0 = sm + 2 * ASZ;
    uint32_t* Xs1 = sm + 2 * ASZ + XSZ;

    const int z   = blockIdx.z;
    const int m0g = blockIdx.y * 128;
    const int n0  = blockIdx.x * 128;
    if (AzStride) Ap += (size_t)(z >> 1) * AzStride;
    X += (size_t)z * (size_t)Kd * N;
    int m0;
    if (YSPLIT) {
        Y += ((size_t)(m0g >> 10) * BXC + z) * (size_t)1024 * N;
        m0 = m0g & 1023;
    } else {
        Y += (size_t)z * (size_t)M * N;
        m0 = m0g;
    }

    const int tid  = threadIdx.x;
    const int lane = tid & 31;
    const int w    = tid >> 5;
    const int wM   = (w >> 2) * 64;
    const int wN   = (w & 3) * 32;
    const int g    = lane >> 2;
    const int tig  = lane & 3;

    const int am   = tid >> 1;
    const int ah   = tid & 1;
    const uint32_t* agp = Ap + (size_t)(m0g + am) * ApS + ah * 8;
    uint32_t asm0 = (uint32_t)__cvta_generic_to_shared(As0 + am * AST + ah * 8);
    uint32_t asm1 = (uint32_t)__cvta_generic_to_shared(As1 + am * AST + ah * 8);

    // ldmatrix per-lane base: row = wM + (lane&15), col-block = (lane>>4)*4 u32
    uint32_t lm0 = (uint32_t)__cvta_generic_to_shared(
        As0 + (wM + (lane & 15)) * AST + ((lane >> 4) << 2));
    uint32_t lm1 = (uint32_t)__cvta_generic_to_shared(
        As1 + (wM + (lane & 15)) * AST + ((lane >> 4) << 2));

    const int kpa = tid >> 5;
    const int nqa = tid & 31;
    const int kpb = kpa + 8;
    const float* xga = X + (size_t)(2 * kpa) * N + n0 + 4 * nqa;
    const float* xgb = X + (size_t)(2 * kpb) * N + n0 + 4 * nqa;

    float c[4][4][4];
#pragma unroll
    for (int i = 0; i < 4; i++)
#pragma unroll
        for (int j = 0; j < 4; j++)
#pragma unroll
            for (int q = 0; q < 4; q++) c[i][j][q] = 0.0f;

    uint32_t xu[2][4];
    uint32_t xh[2];

    auto ldA = [&](int st, int ck) {
        const uint32_t* s0 = agp + (size_t)ck * 16;
        uint32_t d0 = (st ? asm1 : asm0);
#pragma unroll
        for (int t = 0; t < TAPS; t++) {
            CP16(d0 + t * 16 * 4, s0 + t * (Kd / 2));
            CP16(d0 + t * 16 * 4 + 16, s0 + t * (Kd / 2) + 4);
        }
    };

    auto ldX = [&](int ck) {
        const float* p0 = xga + (size_t)(ck * 32) * N;
        const float* p1 = xgb + (size_t)(ck * 32) * N;
        float4 r0 = *(const float4*)p0;
        float4 r1 = *(const float4*)(p0 + N);
        xu[0][0] = pk(r0.x, r1.x); xu[0][1] = pk(r0.y, r1.y);
        xu[0][2] = pk(r0.z, r1.z); xu[0][3] = pk(r0.w, r1.w);
        float4 r2 = *(const float4*)p1;
        float4 r3 = *(const float4*)(p1 + N);
        xu[1][0] = pk(r2.x, r3.x); xu[1][1] = pk(r2.y, r3.y);
        xu[1][2] = pk(r2.z, r3.z); xu[1][3] = pk(r2.w, r3.w);
        if (TAPS == 3) {
            if (tid < 16) {
                if (n0 > 0) {
                    const float* h0 = X + (size_t)(ck * 32 + 2 * tid) * N + n0 - 2;
                    const float* h1 = h0 + N;
                    xh[0] = pk(h0[0], h1[0]);
                    xh[1] = pk(h0[1], h1[1]);
                } else {
                    xh[0] = 0u; xh[1] = 0u;
                }
            }
        }
    };

    auto stX = [&](int st) {
        uint32_t* Xb = st ? Xs1 : Xs0;
        *(uint4*)&Xb[kpa * XST + XOFF + 4 * nqa] = make_uint4(xu[0][0], xu[0][1], xu[0][2], xu[0][3]);
        *(uint4*)&Xb[kpb * XST + XOFF + 4 * nqa] = make_uint4(xu[1][0], xu[1][1], xu[1][2], xu[1][3]);
        if (TAPS == 3) {
            if (tid < 16) {
                Xb[tid * XST + 2] = xh[0];
                Xb[tid * XST + 3] = xh[1];
            }
        }
    };

    auto compute = [&](int st) {
        const uint32_t* Xb = st ? Xs1 : Xs0;
        uint32_t lmB = st ? lm1 : lm0;
#pragma unroll
        for (int t = 0; t < TAPS; t++) {
#pragma unroll
            for (int s = 0; s < 2; s++) {
                uint32_t af[4][4];
#pragma unroll
                for (int i = 0; i < 4; i++) {
                    uint32_t addr = lmB + (uint32_t)((i * 16 * AST + t * 16 + s * 8) * 4);
                    ldsm4(af[i][0], af[i][1], af[i][2], af[i][3], addr);
                }
                uint32_t bf[4][2];
                const uint32_t* q0 = Xb + (s * 8 + tig) * XST + XOFF + (t - (TAPS - 1)) + wN + g;
#pragma unroll
                for (int j = 0; j < 4; j++) {
                    bf[j][0] = q0[j * 8];
                    bf[j][1] = q0[4 * XST + j * 8];
                }
#pragma unroll
                for (int i = 0; i < 4; i++)
#pragma unroll
                    for (int j = 0; j < 4; j++)
                        mma_bf16(c[i][j], af[i], bf[j]);
            }
        }
    };

    const int NC = Kd / 32;
    ldA(0, 0); CPCOMMIT();
    ldX(0); stX(0);
    CPWAIT0();
    __syncthreads();

    for (int cc = 0; cc < NC; cc++) {
        int nx = cc + 1;
        if (nx < NC) {
            ldA(nx & 1, nx); CPCOMMIT();
            ldX(nx);
        }
        compute(cc & 1);
        if (nx < NC) {
            stX(nx & 1);
            CPWAIT0();
        }
        __syncthreads();
    }

#pragma unroll
    for (int i = 0; i < 4; i++) {
        int m = m0 + wM + i * 16 + g;
        float bi0 = BIAS ? bias[m] : 0.0f;
        float bi1 = BIAS ? bias[m + 8] : 0.0f;
#pragma unroll
        for (int j = 0; j < 4; j++) {
            int n = n0 + wN + j * 8 + 2 * tig;
            float2 v0 = make_float2(c[i][j][0] + bi0, c[i][j][1] + bi0);
            float2 v1 = make_float2(c[i][j][2] + bi1, c[i][j][3] + bi1);
            if (RELU) {
                v0.x = fmaxf(v0.x, 0.0f); v0.y = fmaxf(v0.y, 0.0f);
                v1.x = fmaxf(v1.x, 0.0f); v1.y = fmaxf(v1.y, 0.0f);
            }
            *(float2*)&Y[(size_t)m * N + n]       = v0;
            *(float2*)&Y[(size_t)(m + 8) * N + n] = v1;
        }
    }
}

// ========== combine: coalesced two-pass, thread-per-s-column ==================
template <bool LAST>
__global__ __launch_bounds__(256)
void combine2() {
    __shared__ float sTd[4][64], sSu[4][64], sSuu[4][64];
    __shared__ float sSusc[4][64], sSsc[4][64], sSscsc[4][64];
    __shared__ float sOff[4][64], sMean[64], sInvd[64];

    const int scol = threadIdx.x & 63;
    const int part = threadIdx.x >> 6;
    const int b = blockIdx.y;
    const int s = blockIdx.x * 64 + scol;
    const float inv = 1.0f / (float)(s + 1);
    const size_t base = (size_t)b * FXC * SXC + s;
    const size_t DS1 = (size_t)BXC * FXC * SXC;
    const int f0 = part * 128;

    float cum = 0.0f, Su = 0.0f, Suu = 0.0f, Susc = 0.0f, Ssc = 0.0f, Sscsc = 0.0f;
#pragma unroll 4
    for (int j = 0; j < 128; j++) {
        size_t id = base + (size_t)(f0 + j) * SXC;
        float dv = g_ds3[id];
        float sc = g_ds3[id + DS1];
        float sh = g_ds3[id + 2 * DS1];
        cum += dv;
        float u = cum * inv * sc + sh;
        Su += u; Suu += u * u; Susc += u * sc;
        Ssc += sc; Sscsc += sc * sc;
    }
    sTd[part][scol] = cum;
    sSu[part][scol] = Su;     sSuu[part][scol] = Suu;
    sSusc[part][scol] = Susc; sSsc[part][scol] = Ssc;
    sSscsc[part][scol] = Sscsc;
    __syncthreads();

    if (part == 0) {
        float off = 0.0f, S1 = 0.0f, S2 = 0.0f;
#pragma unroll
        for (int p = 0; p < 4; p++) {
            sOff[p][scol] = off;
            float cp = off * inv;
            S1 += sSu[p][scol] + cp * sSsc[p][scol];
            S2 += sSuu[p][scol] + 2.0f * cp * sSusc[p][scol] + cp * cp * sSscsc[p][scol];
            off += sTd[p][scol];
        }
        float mean = S1 * (1.0f / (float)FXC);
        float ssq = fmaxf(S2 - S1 * mean, 0.0f);
        float denom = sqrtf(ssq) * rsqrtf((float)FXC) + 1e-5f;
        sMean[scol] = mean;
        sInvd[scol] = 1.0f / denom;
    }
    __syncthreads();

    const float INIT_SCALE = 0.7071067811865476f;
    const float BETA = 0.99f;
    float off  = sOff[part][scol];
    float mean = sMean[scol];
    float invd = sInvd[scol];
    float cum2 = off;
#pragma unroll 4
    for (int j = 0; j < 128; j++) {
        int f = f0 + j;
        size_t id = base + (size_t)f * SXC;
        float dv = g_ds3[id];
        float sc = g_ds3[id + DS1];
        float sh = g_ds3[id + 2 * DS1];
        cum2 += dv;
        float val = cum2 * inv * sc + sh;
        float cell = (val - mean) * invd * INIT_SCALE;
        float cnew = BETA * g_a[id] + (1.0f - BETA) * cell;
        g_a[id] = cnew;
        float nb = g_b[id] + cnew;
        g_b[id] = nb;
        if (LAST) {
            size_t sb = ((size_t)b * 2 * FXC + f) * SXC + s;
            g_str[sb] = cnew;
            g_str[sb + (size_t)FXC * SXC] = nb;
        } else {
            g_h[id] = nb + g_fe[f];
        }
    }
}

// ---------------- per-position NLL -------------------------------------------
__global__ void nll_kernel(const int* __restrict__ tgt) {
    int bs = blockIdx.x;
    int b = bs >> 11;
    int s = bs & 2047;
    int c = threadIdx.x;
    float x = g_log[((size_t)b * CXC + c) * SXC + s];

    int lane = c & 31, wid = c >> 5;
    __shared__ float red[8];
    __shared__ float bc[2];
    __shared__ float tval;

    float m = x;
#pragma unroll
    for (int o = 16; o > 0; o >>= 1) m = fmaxf(m, __shfl_xor_sync(0xffffffffu, m, o));
    if (lane == 0) red[wid] = m;
    __syncthreads();
    if (c == 0) {
        float t2 = red[0];
        for (int i = 1; i < 8; i++) t2 = fmaxf(t2, red[i]);
        bc[0] = t2;
    }
    __syncthreads();
    float e = expf(x - bc[0]);
#pragma unroll
    for (int o = 16; o > 0; o >>= 1) e += __shfl_xor_sync(0xffffffffu, e, o);
    __syncthreads();
    if (lane == 0) red[wid] = e;
    int tv = tgt[b * SXC + s];
    if (c == tv) tval = x;
    __syncthreads();
    if (c == 0) {
        float t2 = 0.0f;
        for (int i = 0; i < 8; i++) t2 += red[i];
        float lse = bc[0] + logf(t2);
        g_nll[bs] = lse - tval;
    }
}

// ---------------- deterministic final mean -----------------------------------
__global__ void reduce_kernel(float* __restrict__ out) {
    __shared__ float sh[1024];
    int t = threadIdx.x;
    float s = 0.0f;
    for (int i = t; i < BXC * SXC; i += 1024) s += g_nll[i];
    sh[t] = s;
    __syncthreads();
    for (int o = 512; o > 0; o >>= 1) {
        if (t < o) sh[t] += sh[t + o];
        __syncthreads();
    }
    if (t == 0) out[0] = sh[0] / (float)(BXC * SXC);
}

// ---------------- host orchestration -----------------------------------------
extern "C" void kernel_launch(void* const* d_in, const int* in_sizes, int n_in,
                              void* d_out, int out_size) {
    const int*   inp   = (const int*)d_in[0];
    const int*   tgt   = (const int*)d_in[1];
    const float* emb   = (const float*)d_in[2];
    const float* w0s   = (const float*)d_in[3];
    const float* w1s   = (const float*)d_in[4];
    const float* w2s   = (const float*)d_in[5];
    const float* out_w = (const float*)d_in[6];
    const float* out_b = (const float*)d_in[7];
    float* out = (float*)d_out;

    float *ph, *py1, *py2, *pds, *pstr, *plog;
    uint32_t *pw0, *pw3, *pw2, *pwL;
    cudaGetSymbolAddress((void**)&ph,  g_h);
    cudaGetSymbolAddress((void**)&py1, g_y1);
    cudaGetSymbolAddress((void**)&py2, g_y2);
    cudaGetSymbolAddress((void**)&pds, g_ds3);
    cudaGetSymbolAddress((void**)&pstr, g_str);
    cudaGetSymbolAddress((void**)&plog, g_log);
    cudaGetSymbolAddress((void**)&pw0, g_wp0);
    cudaGetSymbolAddress((void**)&pw3, g_wp3);
    cudaGetSymbolAddress((void**)&pw2, g_wp2);
    cudaGetSymbolAddress((void**)&pwL, g_wpL);

    const int SM_T3 = (2 * (128 * 52) + 2 * (16 * 136)) * 4;   // 70656
    const int SM_T1 = (2 * (128 * 20) + 2 * (16 * 136)) * 4;   // 37888

    cudaFuncSetAttribute((const void*)mmbf<1, true,  false, true>,
                         cudaFuncAttributeMaxDynamicSharedMemorySize, SM_T1);
    cudaFuncSetAttribute((const void*)mmbf<3, true,  false, false>,
                         cudaFuncAttributeMaxDynamicSharedMemorySize, SM_T3);
    cudaFuncSetAttribute((const void*)mmbf<1, false, false, false>,
                         cudaFuncAttributeMaxDynamicSharedMemorySize, SM_T1);
    cudaFuncSetAttribute((const void*)mmbf<1, false, true,  false>,
                         cudaFuncAttributeMaxDynamicSharedMemorySize, SM_T1);

    // ---- launch 1: all weight packs + fe ----
    {
        int total = 6*IXC*3*(IXC/2) + 6*IXC*(FXC/2) + 6*FXC*(IXC/2) + CXC*FXC + FXC;
        pack_all<<<(total + 255) / 256, 256>>>(w1s, w0s, w2s, out_w);
    }
    // ---- launch 2: embedding ----
    {
        size_t n = (size_t)BXC * FXC * SXC;
        embed_kernel<<<(unsigned)((n + 255) / 256), 256>>>(inp, emb);
    }

    const size_t AzS3 = (size_t)IXC * 3 * (IXC/2);
    const size_t AzS2 = (size_t)FXC * (IXC/2);

    for (int l = 0; l < LXC; ++l) {
        const uint32_t* W0 = pw0 + (size_t)l * 3 * IXC * (FXC/2);
        const uint32_t* W3 = pw3 + (size_t)l * 3 * AzS3;
        const uint32_t* W2 = pw2 + (size_t)l * 3 * AzS2;

        // conv0: all 3 branches merged, M = 3072, Y split to [branch][b][i][s]
        dim3 grid0(SXC / 128, (3 * IXC) / 128, BXC);            // 16 x 24 x 2
        mmbf<1, true, false, true><<<grid0, 256, SM_T1>>>(
            W0, ph, py1, nullptr, 3 * IXC, FXC, SXC, FXC/2, 0);
        // conv1: causal k=3, z-batched over branch*B + b
        dim3 grid1(SXC / 128, IXC / 128, 3 * BXC);              // 16 x 8 x 6
        mmbf<3, true, false, false><<<grid1, 256, SM_T3>>>(
            W3, py1, py2, nullptr, IXC, IXC, SXC, 3 * (IXC/2), AzS3);
        // conv2: z-batched, writes [branch][b][f][s] into g_ds3
        dim3 grid2(SXC / 128, FXC / 128, 3 * BXC);              // 16 x 4 x 6
        mmbf<1, false, false, false><<<grid2, 256, SM_T1>>>(
            W2, py2, pds, nullptr, FXC, IXC, SXC, IXC/2, AzS2);

        dim3 gridCB(SXC / 64, BXC);
        if (l == LXC - 1) combine2<true><<<gridCB, 256>>>();
        else              combine2<false><<<gridCB, 256>>>();
    }

    {
        dim3 gridC(SXC / 128, CXC / 128, BXC);                  // 16 x 2 x 2
        mmbf<1, false, true, false><<<gridC, 256, SM_T1>>>(
            pwL, pstr, plog, out_b, CXC, 2 * FXC, SXC, FXC, 0);
    }
    nll_kernel<<<BXC * SXC, 256>>>(tgt);
    reduce_kernel<<<1, 1024>>>(out);
}